// round 4
// baseline (speedup 1.0000x reference)
#include <cuda_runtime.h>
#include <math.h>

#define N_TOTAL 4096
#define T_ 32
#define D_ 158
#define NEWS_ 1024
#define AGGW 1184          // 1024 news + 158 price + 2 pad (74 * 16)
#define KSPLIT 4
#define NKT 74

// out layout (float32): pred | rw | hidden | topk | rw
#define OFF_PRED 0
#define OFF_RW1 4096
#define OFF_HID 266240
#define OFF_TOPK 528384
#define OFF_RW2 536576

__device__ float g_agg[N_TOTAL * AGGW];
__device__ float g_part[KSPLIT * N_TOTAL * 128];
__device__ int   g_flag[N_TOTAL];

// ---------------------------------------------------------------------------
__global__ void zeroFlags() {
    int i = blockIdx.x * blockDim.x + threadIdx.x;
    if (i < N_TOTAL) g_flag[i] = 0;
}

// ---------------------------------------------------------------------------
// Fused kernel: bid%5==0 -> GEMM role (1024 blocks), else aggregation role
// (4096 blocks, one row each). Per-row flags synchronize producer->consumer.
// ---------------------------------------------------------------------------
extern __shared__ unsigned char dynsmem[];

struct GS { float A[2][16][16]; float B[2][16][128]; };   // 18432 B

__global__ void __launch_bounds__(256, 3)
fusedAB(const float* __restrict__ price,
        const float* __restrict__ news,
        const float* __restrict__ maskp,
        const float* __restrict__ router_W) {
    const int bid = blockIdx.x;
    const int tid = threadIdx.x;

    if (bid % 5 != 0) {
        // ---------------- aggregation role: one row n ----------------
        const int n = bid - bid / 5 - 1;
        float* sm = (float*)dynsmem;   // [33]
        if (tid < T_) sm[tid] = maskp[n * T_ + tid];
        __syncthreads();
        if (tid == 0) {
            float s = 0.f;
            #pragma unroll
            for (int t = 0; t < T_; t++) s += sm[t];
            sm[32] = 1.0f / fmaxf(s, 1e-6f);
        }
        __syncthreads();

        const float4* news4 = (const float4*)(news + (size_t)n * T_ * NEWS_);
        float4 acc = make_float4(0.f, 0.f, 0.f, 0.f);
        #pragma unroll 4
        for (int t = 0; t < T_; t++) {
            float mt = sm[t];
            float4 v = news4[t * 256 + tid];
            acc.x += mt * v.x; acc.y += mt * v.y;
            acc.z += mt * v.z; acc.w += mt * v.w;
        }
        float inv = sm[32];
        acc.x *= inv; acc.y *= inv; acc.z *= inv; acc.w *= inv;
        ((float4*)(g_agg + (size_t)n * AGGW))[tid] = acc;

        if (tid < D_) {
            const float* p = price + (size_t)n * T_ * D_ + tid;
            float a = 0.f;
            #pragma unroll 4
            for (int t = 0; t < T_; t++) a += p[t * D_];
            g_agg[(size_t)n * AGGW + NEWS_ + tid] = a * (1.0f / 32.0f);
        } else if (tid < 160) {
            g_agg[(size_t)n * AGGW + NEWS_ + tid] = 0.0f;
        }
        __threadfence();
        __syncthreads();
        if (tid == 0) atomicExch(&g_flag[n], 1);
    } else {
        // ---------------- GEMM role: 16 rows x 128 cols, K-split ----------------
        const int g = bid / 5;
        const int ks = g & 3;
        const int n0 = (g >> 2) * 16;
        const int kt0 = (ks * NKT) / 4;
        const int kt1 = ((ks + 1) * NKT) / 4;
        GS& s = *(GS*)dynsmem;

        if (tid < 16) {
            while (atomicAdd(&g_flag[n0 + tid], 0) == 0) { }
            __threadfence();
        }
        __syncthreads();

        const int ar = tid >> 4, ac = tid & 15;
        float ra, rbw[8];

        // prologue: tile kt0
        {
            int k0 = kt0 * 16;
            ra = g_agg[(size_t)(n0 + ar) * AGGW + k0 + ac];
            #pragma unroll
            for (int i = 0; i < 8; i++) {
                int idx = tid + i * 256;
                int kk = idx >> 7, j = idx & 127;
                int krow = k0 + kk;
                int wrow = (krow < 1024) ? (158 + krow) : min(krow - 1024, 157);
                rbw[i] = router_W[wrow * 128 + j];
            }
            s.A[0][ar][ac] = ra;
            #pragma unroll
            for (int i = 0; i < 8; i++) {
                int idx = tid + i * 256;
                s.B[0][idx >> 7][idx & 127] = rbw[i];
            }
        }
        __syncthreads();

        const int tr = tid >> 5;   // warp id: rows 2*tr, 2*tr+1
        const int tc = tid & 31;   // cols tc*4..
        float acc0[4] = {0, 0, 0, 0}, acc1[4] = {0, 0, 0, 0};

        for (int t = kt0; t < kt1; t++) {
            const int cur = (t - kt0) & 1;
            if (t + 1 < kt1) {
                int k0 = (t + 1) * 16;
                ra = g_agg[(size_t)(n0 + ar) * AGGW + k0 + ac];
                #pragma unroll
                for (int i = 0; i < 8; i++) {
                    int idx = tid + i * 256;
                    int kk = idx >> 7, j = idx & 127;
                    int krow = k0 + kk;
                    int wrow = (krow < 1024) ? (158 + krow) : min(krow - 1024, 157);
                    rbw[i] = router_W[wrow * 128 + j];
                }
            }
            #pragma unroll
            for (int k = 0; k < 16; k++) {
                float a0 = s.A[cur][2 * tr][k];
                float a1 = s.A[cur][2 * tr + 1][k];
                float4 b = *(const float4*)&s.B[cur][k][tc * 4];
                acc0[0] += a0 * b.x; acc0[1] += a0 * b.y;
                acc0[2] += a0 * b.z; acc0[3] += a0 * b.w;
                acc1[0] += a1 * b.x; acc1[1] += a1 * b.y;
                acc1[2] += a1 * b.z; acc1[3] += a1 * b.w;
            }
            if (t + 1 < kt1) {
                const int nxt = cur ^ 1;
                s.A[nxt][ar][ac] = ra;
                #pragma unroll
                for (int i = 0; i < 8; i++) {
                    int idx = tid + i * 256;
                    s.B[nxt][idx >> 7][idx & 127] = rbw[i];
                }
            }
            __syncthreads();
        }

        float* pp = g_part + ((size_t)ks * N_TOTAL + n0) * 128;
        *(float4*)&pp[(2 * tr) * 128 + tc * 4]     = *(float4*)acc0;
        *(float4*)&pp[(2 * tr + 1) * 128 + tc * 4] = *(float4*)acc1;
    }
}

// ---------------------------------------------------------------------------
// Epilogue: reduce K-split partials + tanh + gate GEMM + topk/softmax/
// experts/attention/output. 128 blocks x 256 threads.
// ---------------------------------------------------------------------------
struct SmemC {
    float h[32][128];               // 16 KB
    float gate[128][64];            // 32 KB
    float wexp[64][64];             // 16 KB  [h][g*8+e]
    float wq[8][64], wk[8][64], wv[8][64], wo[8][64];  // 8 KB [e][g*8+f]
    float eb[64], qb[64], kb[64], vb[64], ob[64], gb[64];
    float rb[128];
    float h32[32][64];              // 8 KB
    float eo[4][64], q[4][64], kk_[4][64], v[4][64], att[4][64], wbuf[4][64];
    int   i1[4], i2[4];
    float v1[4], den[4];
};

__global__ void __launch_bounds__(256, 1)
kernelC(const float* __restrict__ router_b,
        const float* __restrict__ gate_W,
        const float* __restrict__ gate_b,
        const float* __restrict__ expert_W,
        const float* __restrict__ expert_b,
        const float* __restrict__ wq, const float* __restrict__ wq_b,
        const float* __restrict__ wk, const float* __restrict__ wk_b,
        const float* __restrict__ wv, const float* __restrict__ wv_b,
        const float* __restrict__ wo, const float* __restrict__ wo_b,
        float* __restrict__ out) {
    SmemC& s = *reinterpret_cast<SmemC*>(dynsmem);
    const int tid = threadIdx.x;
    const int n0 = blockIdx.x * 32;

    // ---- stage weights ----
    for (int idx = tid; idx < 128 * 64; idx += 256)
        s.gate[idx >> 6][idx & 63] = gate_W[idx];
    for (int idx = tid; idx < 4096; idx += 256) {
        int ge = idx >> 6, h = idx & 63;
        s.wexp[h][ge] = expert_W[idx];
    }
    for (int idx = tid; idx < 512; idx += 256) {
        int g = idx >> 6, f = (idx >> 3) & 7, e = idx & 7;
        int dst = e * 64 + g * 8 + f;
        ((float*)s.wq)[dst] = wq[idx];
        ((float*)s.wk)[dst] = wk[idx];
        ((float*)s.wv)[dst] = wv[idx];
        ((float*)s.wo)[dst] = wo[idx];
    }
    if (tid < 64) {
        s.eb[tid] = expert_b[tid];
        s.qb[tid] = wq_b[tid]; s.kb[tid] = wk_b[tid];
        s.vb[tid] = wv_b[tid]; s.ob[tid] = wo_b[tid];
        s.gb[tid] = gate_b[tid];
    }
    if (tid < 128) s.rb[tid] = router_b[tid];
    __syncthreads();

    // ---- reduce partials + tanh ----
    for (int idx = tid; idx < 32 * 128; idx += 256) {
        int r = idx >> 7, j = idx & 127;
        size_t off = (size_t)(n0 + r) * 128 + j;
        float v = g_part[off]
                + g_part[(size_t)1 * N_TOTAL * 128 + off]
                + g_part[(size_t)2 * N_TOTAL * 128 + off]
                + g_part[(size_t)3 * N_TOTAL * 128 + off];
        s.h[r][j] = tanhf(v + s.rb[j]);
    }
    __syncthreads();

    // ---- gate GEMM: hidden[32][64] ----
    {
        int r = tid >> 3;
        int c0 = (tid & 7) * 8;
        float hacc[8] = {};
        #pragma unroll 4
        for (int kk = 0; kk < 128; kk++) {
            float hv = s.h[r][kk];
            float4 g0 = *(const float4*)&s.gate[kk][c0];
            float4 g1 = *(const float4*)&s.gate[kk][c0 + 4];
            hacc[0] += hv * g0.x; hacc[1] += hv * g0.y;
            hacc[2] += hv * g0.z; hacc[3] += hv * g0.w;
            hacc[4] += hv * g1.x; hacc[5] += hv * g1.y;
            hacc[6] += hv * g1.z; hacc[7] += hv * g1.w;
        }
        float* out_hid = out + OFF_HID;
        #pragma unroll
        for (int c = 0; c < 8; c++) {
            float val = hacc[c] + s.gb[c0 + c];
            out_hid[(size_t)(n0 + r) * 64 + c0 + c] = val;
            s.h32[r][c0 + c] = val;
        }
    }
    __syncthreads();

    // ---- topk / softmax / experts / attention / output ----
    {
        const int grp = tid >> 6;
        const int j = tid & 63;
        const int g = j >> 3;
        const int base = g * 8;
        const int hh = (j & 7) >> 1, d = j & 1;

        float* out_pred = out + OFF_PRED;
        float* out_rw1 = out + OFF_RW1;
        float* out_topk = out + OFF_TOPK;
        float* out_rw2 = out + OFF_RW2;

        for (int it = 0; it < 8; it++) {
            int rl = it * 4 + grp;
            int n = n0 + rl;
            float hj = s.h32[rl][j];

            if (j == 0) {
                float v1 = -1e38f; int i1 = 0;
                #pragma unroll 8
                for (int a = 0; a < 64; a++) {
                    float v = s.h32[rl][a];
                    if (v > v1) { v1 = v; i1 = a; }
                }
                float v2 = -1e38f; int i2 = 0;
                #pragma unroll 8
                for (int a = 0; a < 64; a++) {
                    if (a == i1) continue;
                    float v = s.h32[rl][a];
                    if (v > v2) { v2 = v; i2 = a; }
                }
                s.i1[grp] = i1; s.i2[grp] = i2; s.v1[grp] = v1;
                s.den[grp] = 1.0f + expf(v2 - v1);
            }
            __syncthreads();
            int i1 = s.i1[grp], i2 = s.i2[grp];
            float rw = 0.0f;
            if (j == i1) rw = 1.0f / s.den[grp];
            else if (j == i2) rw = expf(hj - s.v1[grp]) / s.den[grp];

            float eo = s.eb[j];
            #pragma unroll 8
            for (int h = 0; h < 64; h++) eo += s.h32[rl][h] * s.wexp[h][j];
            s.eo[grp][j] = eo;
            __syncthreads();

            float qv = s.qb[j], kv = s.kb[j], vv = s.vb[j];
            #pragma unroll
            for (int e = 0; e < 8; e++) {
                float x = s.eo[grp][base + e];
                qv += x * s.wq[e][j];
                kv += x * s.wk[e][j];
                vv += x * s.wv[e][j];
            }
            s.q[grp][j] = qv; s.kk_[grp][j] = kv; s.v[grp][j] = vv;
            __syncthreads();

            float s0 = 0.f, s1 = 0.f;
            #pragma unroll
            for (int a = 0; a < 4; a++) {
                float qa = s.q[grp][base + 2 * a + d];
                s0 += qa * s.kk_[grp][base + 2 * a];
                s1 += qa * s.kk_[grp][base + 2 * a + 1];
            }
            const float sc = 0.70710678118654752440f;
            s0 *= sc; s1 *= sc;
            float mx = fmaxf(s0, s1);
            float e0 = expf(s0 - mx), e1 = expf(s1 - mx);
            float rs = 1.0f / (e0 + e1);
            float att = (e0 * rs) * s.v[grp][base + 2 * hh]
                      + (e1 * rs) * s.v[grp][base + 2 * hh + 1];
            s.att[grp][j] = att;
            __syncthreads();

            float ag = s.ob[j];
            #pragma unroll
            for (int e = 0; e < 8; e++) ag += s.att[grp][base + e] * s.wo[e][j];

            out_rw1[(size_t)n * 64 + j] = rw;
            out_rw2[(size_t)n * 64 + j] = rw;
            s.wbuf[grp][j] = ag * rw;
            __syncthreads();
            if (j == 0) {
                out_pred[n] = s.wbuf[grp][i1] + s.wbuf[grp][i2];
                out_topk[n * 2 + 0] = (float)i1;
                out_topk[n * 2 + 1] = (float)i2;
            }
            __syncthreads();
        }
    }
}

// ---------------------------------------------------------------------------
extern "C" void kernel_launch(void* const* d_in, const int* in_sizes, int n_in,
                              void* d_out, int out_size) {
    const float* price    = (const float*)d_in[0];
    const float* news     = (const float*)d_in[1];
    const float* mask     = (const float*)d_in[2];
    const float* router_W = (const float*)d_in[3];
    const float* router_b = (const float*)d_in[4];
    const float* gate_W   = (const float*)d_in[5];
    const float* gate_b   = (const float*)d_in[6];
    const float* expert_W = (const float*)d_in[7];
    const float* expert_b = (const float*)d_in[8];
    const float* wq   = (const float*)d_in[9];
    const float* wq_b = (const float*)d_in[10];
    const float* wk   = (const float*)d_in[11];
    const float* wk_b = (const float*)d_in[12];
    const float* wv   = (const float*)d_in[13];
    const float* wv_b = (const float*)d_in[14];
    const float* wo   = (const float*)d_in[15];
    const float* wo_b = (const float*)d_in[16];
    float* out = (float*)d_out;

    zeroFlags<<<16, 256>>>();

    fusedAB<<<5120, 256, sizeof(GS)>>>(price, news, mask, router_W);

    cudaFuncSetAttribute(kernelC,
                         cudaFuncAttributeMaxDynamicSharedMemorySize,
                         (int)sizeof(SmemC));
    kernelC<<<128, 256, sizeof(SmemC)>>>(
        router_b, gate_W, gate_b, expert_W, expert_b,
        wq, wq_b, wk, wk_b, wv, wv_b, wo, wo_b, out);
}

// round 6
// speedup vs baseline: 1.4003x; 1.4003x over previous
#include <cuda_runtime.h>
#include <math.h>

#define N_TOTAL 4096
#define T_ 32
#define D_ 158
#define NEWS_ 1024
#define AGGW 1184          // 1024 news + 158 price + 2 pad (74 * 16)
#define KSPLIT 4
#define NKT 74
#define NGEMM 1024         // 256 row-tiles * 4 k-splits

// out layout (float32): pred | rw | hidden | topk | rw
#define OFF_PRED 0
#define OFF_RW1 4096
#define OFF_HID 266240
#define OFF_TOPK 528384
#define OFF_RW2 536576

__device__ float g_agg[N_TOTAL * AGGW];
__device__ float g_part[KSPLIT * N_TOTAL * 128];
__device__ int   g_flag[N_TOTAL];   // zero-initialized; kernelC re-zeroes each run

// ---------------------------------------------------------------------------
#define CP_ASYNC16(dst, src) \
    asm volatile("cp.async.cg.shared.global [%0], [%1], 16;\n" \
                 :: "r"(dst), "l"(src))
#define CP_COMMIT() asm volatile("cp.async.commit_group;\n" ::: "memory")
#define CP_WAIT(n)  asm volatile("cp.async.wait_group %0;\n" :: "n"(n) : "memory")

struct GS { float A[2][16][16]; float B[2][16][128]; };   // 18432 B

extern __shared__ unsigned char dynsmem[];

// ---------------------------------------------------------------------------
// fusedAG: bids 0..4095 = aggregation (one row each, full occupancy wave);
//          bids 4096..5119 = router-GEMM tiles that enter as agg retires.
// ---------------------------------------------------------------------------
__global__ void __launch_bounds__(256, 8)
fusedAG(const float* __restrict__ price,
        const float* __restrict__ news,
        const float* __restrict__ maskp,
        const float* __restrict__ router_W) {
    const int bid = blockIdx.x;
    const int tid = threadIdx.x;

    if (bid < N_TOTAL) {
        // ---------------- aggregation role (round-1 proven body) ----------
        const int n = bid;
        float* sm = (float*)dynsmem;   // [33]
        if (tid < T_) sm[tid] = maskp[n * T_ + tid];
        __syncthreads();
        if (tid == 0) {
            float s = 0.f;
            #pragma unroll
            for (int t = 0; t < T_; t++) s += sm[t];
            sm[32] = 1.0f / fmaxf(s, 1e-6f);
        }
        __syncthreads();

        const float4* news4 = (const float4*)(news + (size_t)n * T_ * NEWS_);
        float4 acc = make_float4(0.f, 0.f, 0.f, 0.f);
        #pragma unroll 4
        for (int t = 0; t < T_; t++) {
            float mt = sm[t];
            float4 v = news4[t * 256 + tid];
            acc.x += mt * v.x; acc.y += mt * v.y;
            acc.z += mt * v.z; acc.w += mt * v.w;
        }
        float inv = sm[32];
        acc.x *= inv; acc.y *= inv; acc.z *= inv; acc.w *= inv;
        ((float4*)(g_agg + (size_t)n * AGGW))[tid] = acc;

        if (tid < D_) {
            const float* p = price + (size_t)n * T_ * D_ + tid;
            float a = 0.f;
            #pragma unroll 4
            for (int t = 0; t < T_; t++) a += p[t * D_];
            g_agg[(size_t)n * AGGW + NEWS_ + tid] = a * (1.0f / 32.0f);
        } else if (tid < 160) {
            g_agg[(size_t)n * AGGW + NEWS_ + tid] = 0.0f;
        }
        __threadfence();
        __syncthreads();
        if (tid == 0) atomicExch(&g_flag[n], 1);
    } else {
        // ---------------- GEMM role: 16 rows x 128 cols, K-split 4 --------
        const int g = bid - N_TOTAL;
        const int tile = g >> 2;
        const int ks = g & 3;
        const int n0 = tile * 16;
        const int kt0 = (ks * NKT) / 4;
        const int kt1 = ((ks + 1) * NKT) / 4;
        GS& s = *(GS*)dynsmem;

        if (tid < 16) {
            while (atomicAdd(&g_flag[n0 + tid], 0) == 0) { }
            __threadfence();
        }
        __syncthreads();

        // cp.async tile loader (no register staging; 32-reg budget)
        auto loadTile = [&](int t, int buf) {
            int k0 = t * 16;
            if (tid < 64) {
                int r = tid >> 2, c = (tid & 3) * 4;
                unsigned dst = (unsigned)__cvta_generic_to_shared(&s.A[buf][r][c]);
                CP_ASYNC16(dst, &g_agg[(size_t)(n0 + r) * AGGW + k0 + c]);
            }
            #pragma unroll
            for (int i = 0; i < 2; i++) {
                int idx = tid + i * 256;              // 0..511 chunks of 16B
                int kk = idx >> 5, j = (idx & 31) * 4;
                int krow = k0 + kk;
                int wrow = (krow < 1024) ? (158 + krow) : min(krow - 1024, 157);
                unsigned dst = (unsigned)__cvta_generic_to_shared(&s.B[buf][kk][j]);
                CP_ASYNC16(dst, &router_W[wrow * 128 + j]);
            }
        };

        loadTile(kt0, 0);
        CP_COMMIT();

        const int tr = tid >> 5;   // warp: rows 2tr, 2tr+1
        const int tc = tid & 31;   // cols tc*4..
        float acc0[4] = {0, 0, 0, 0}, acc1[4] = {0, 0, 0, 0};

        for (int t = kt0; t < kt1; t++) {
            const int cur = (t - kt0) & 1;
            if (t + 1 < kt1) {
                loadTile(t + 1, cur ^ 1);
                CP_COMMIT();
                CP_WAIT(1);
            } else {
                CP_WAIT(0);
            }
            __syncthreads();
            #pragma unroll
            for (int k = 0; k < 16; k++) {
                float a0 = s.A[cur][2 * tr][k];
                float a1 = s.A[cur][2 * tr + 1][k];
                float4 b = *(const float4*)&s.B[cur][k][tc * 4];
                acc0[0] += a0 * b.x; acc0[1] += a0 * b.y;
                acc0[2] += a0 * b.z; acc0[3] += a0 * b.w;
                acc1[0] += a1 * b.x; acc1[1] += a1 * b.y;
                acc1[2] += a1 * b.z; acc1[3] += a1 * b.w;
            }
            __syncthreads();
        }

        float* pp = g_part + ((size_t)ks * N_TOTAL + n0) * 128;
        *(float4*)&pp[(2 * tr) * 128 + tc * 4]     = *(float4*)acc0;
        *(float4*)&pp[(2 * tr + 1) * 128 + tc * 4] = *(float4*)acc1;
    }
}

// ---------------------------------------------------------------------------
// kernelC: reduce K-split partials + tanh + gate GEMM + topk/softmax/experts/
// attention/output. 256 blocks x 256 threads, 16 rows per block.
// Also re-zeroes g_flag for the next graph replay.
// ---------------------------------------------------------------------------
struct SmemC {
    float h[16][128];               // 8 KB
    float gate[128][64];            // 32 KB
    float wexp[64][64];             // 16 KB  [h][g*8+e]
    float wq[8][64], wk[8][64], wv[8][64], wo[8][64];  // 8 KB [e][g*8+f]
    float eb[64], qb[64], kb[64], vb[64], ob[64], gb[64];
    float rb[128];
    float h16[16][64];              // 4 KB
    float eo[4][64], q[4][64], kk_[4][64], v[4][64], att[4][64], wbuf[4][64];
    int   i1[4], i2[4];
    float v1[4], den[4];
};

__global__ void __launch_bounds__(256, 2)
kernelC(const float* __restrict__ router_b,
        const float* __restrict__ gate_W,
        const float* __restrict__ gate_b,
        const float* __restrict__ expert_W,
        const float* __restrict__ expert_b,
        const float* __restrict__ wq, const float* __restrict__ wq_b,
        const float* __restrict__ wk, const float* __restrict__ wk_b,
        const float* __restrict__ wv, const float* __restrict__ wv_b,
        const float* __restrict__ wo, const float* __restrict__ wo_b,
        float* __restrict__ out) {
    SmemC& s = *reinterpret_cast<SmemC*>(dynsmem);
    const int tid = threadIdx.x;
    const int n0 = blockIdx.x * 16;

    // ---- stage weights ----
    for (int idx = tid; idx < 128 * 64; idx += 256)
        s.gate[idx >> 6][idx & 63] = gate_W[idx];
    for (int idx = tid; idx < 4096; idx += 256) {
        int ge = idx >> 6, h = idx & 63;
        s.wexp[h][ge] = expert_W[idx];
    }
    for (int idx = tid; idx < 512; idx += 256) {
        int g = idx >> 6, f = (idx >> 3) & 7, e = idx & 7;
        int dst = e * 64 + g * 8 + f;
        ((float*)s.wq)[dst] = wq[idx];
        ((float*)s.wk)[dst] = wk[idx];
        ((float*)s.wv)[dst] = wv[idx];
        ((float*)s.wo)[dst] = wo[idx];
    }
    if (tid < 64) {
        s.eb[tid] = expert_b[tid];
        s.qb[tid] = wq_b[tid]; s.kb[tid] = wk_b[tid];
        s.vb[tid] = wv_b[tid]; s.ob[tid] = wo_b[tid];
        s.gb[tid] = gate_b[tid];
    }
    if (tid < 128) s.rb[tid] = router_b[tid];
    __syncthreads();

    // ---- reduce partials + tanh ----
    for (int idx = tid; idx < 16 * 128; idx += 256) {
        int r = idx >> 7, j = idx & 127;
        size_t off = (size_t)(n0 + r) * 128 + j;
        float v = g_part[off]
                + g_part[(size_t)1 * N_TOTAL * 128 + off]
                + g_part[(size_t)2 * N_TOTAL * 128 + off]
                + g_part[(size_t)3 * N_TOTAL * 128 + off];
        s.h[r][j] = tanhf(v + s.rb[j]);
    }
    __syncthreads();

    // ---- gate GEMM: hidden[16][64] ----
    {
        int r = tid >> 4;
        int c0 = (tid & 15) * 4;
        float hacc[4] = {};
        #pragma unroll 4
        for (int kk = 0; kk < 128; kk++) {
            float hv = s.h[r][kk];
            float4 g0 = *(const float4*)&s.gate[kk][c0];
            hacc[0] += hv * g0.x; hacc[1] += hv * g0.y;
            hacc[2] += hv * g0.z; hacc[3] += hv * g0.w;
        }
        float* out_hid = out + OFF_HID;
        #pragma unroll
        for (int c = 0; c < 4; c++) {
            float val = hacc[c] + s.gb[c0 + c];
            out_hid[(size_t)(n0 + r) * 64 + c0 + c] = val;
            s.h16[r][c0 + c] = val;
        }
    }
    __syncthreads();

    // ---- topk / softmax / experts / attention / output ----
    {
        const int grp = tid >> 6;
        const int j = tid & 63;
        const int g = j >> 3;
        const int base = g * 8;
        const int hh = (j & 7) >> 1, d = j & 1;

        float* out_pred = out + OFF_PRED;
        float* out_rw1 = out + OFF_RW1;
        float* out_topk = out + OFF_TOPK;
        float* out_rw2 = out + OFF_RW2;

        for (int it = 0; it < 4; it++) {
            int rl = it * 4 + grp;
            int n = n0 + rl;
            float hj = s.h16[rl][j];

            if (j == 0) {
                float v1 = -1e38f; int i1 = 0;
                #pragma unroll 8
                for (int a = 0; a < 64; a++) {
                    float v = s.h16[rl][a];
                    if (v > v1) { v1 = v; i1 = a; }
                }
                float v2 = -1e38f; int i2 = 0;
                #pragma unroll 8
                for (int a = 0; a < 64; a++) {
                    if (a == i1) continue;
                    float v = s.h16[rl][a];
                    if (v > v2) { v2 = v; i2 = a; }
                }
                s.i1[grp] = i1; s.i2[grp] = i2; s.v1[grp] = v1;
                s.den[grp] = 1.0f + expf(v2 - v1);
            }
            __syncthreads();
            int i1 = s.i1[grp], i2 = s.i2[grp];
            float rw = 0.0f;
            if (j == i1) rw = 1.0f / s.den[grp];
            else if (j == i2) rw = expf(hj - s.v1[grp]) / s.den[grp];

            float eo = s.eb[j];
            #pragma unroll 8
            for (int h = 0; h < 64; h++) eo += s.h16[rl][h] * s.wexp[h][j];
            s.eo[grp][j] = eo;
            __syncthreads();

            float qv = s.qb[j], kv = s.kb[j], vv = s.vb[j];
            #pragma unroll
            for (int e = 0; e < 8; e++) {
                float x = s.eo[grp][base + e];
                qv += x * s.wq[e][j];
                kv += x * s.wk[e][j];
                vv += x * s.wv[e][j];
            }
            s.q[grp][j] = qv; s.kk_[grp][j] = kv; s.v[grp][j] = vv;
            __syncthreads();

            float s0 = 0.f, s1 = 0.f;
            #pragma unroll
            for (int a = 0; a < 4; a++) {
                float qa = s.q[grp][base + 2 * a + d];
                s0 += qa * s.kk_[grp][base + 2 * a];
                s1 += qa * s.kk_[grp][base + 2 * a + 1];
            }
            const float sc = 0.70710678118654752440f;
            s0 *= sc; s1 *= sc;
            float mx = fmaxf(s0, s1);
            float e0 = expf(s0 - mx), e1 = expf(s1 - mx);
            float rs = 1.0f / (e0 + e1);
            float att = (e0 * rs) * s.v[grp][base + 2 * hh]
                      + (e1 * rs) * s.v[grp][base + 2 * hh + 1];
            s.att[grp][j] = att;
            __syncthreads();

            float ag = s.ob[j];
            #pragma unroll
            for (int e = 0; e < 8; e++) ag += s.att[grp][base + e] * s.wo[e][j];

            out_rw1[(size_t)n * 64 + j] = rw;
            out_rw2[(size_t)n * 64 + j] = rw;
            s.wbuf[grp][j] = ag * rw;
            __syncthreads();
            if (j == 0) {
                out_pred[n] = s.wbuf[grp][i1] + s.wbuf[grp][i2];
                out_topk[n * 2 + 0] = (float)i1;
                out_topk[n * 2 + 1] = (float)i2;
            }
            __syncthreads();
        }
    }

    // re-zero this block's flags for the next graph replay
    if (tid < 16) g_flag[n0 + tid] = 0;
}

// ---------------------------------------------------------------------------
extern "C" void kernel_launch(void* const* d_in, const int* in_sizes, int n_in,
                              void* d_out, int out_size) {
    const float* price    = (const float*)d_in[0];
    const float* news     = (const float*)d_in[1];
    const float* mask     = (const float*)d_in[2];
    const float* router_W = (const float*)d_in[3];
    const float* router_b = (const float*)d_in[4];
    const float* gate_W   = (const float*)d_in[5];
    const float* gate_b   = (const float*)d_in[6];
    const float* expert_W = (const float*)d_in[7];
    const float* expert_b = (const float*)d_in[8];
    const float* wq   = (const float*)d_in[9];
    const float* wq_b = (const float*)d_in[10];
    const float* wk   = (const float*)d_in[11];
    const float* wk_b = (const float*)d_in[12];
    const float* wv   = (const float*)d_in[13];
    const float* wv_b = (const float*)d_in[14];
    const float* wo   = (const float*)d_in[15];
    const float* wo_b = (const float*)d_in[16];
    float* out = (float*)d_out;

    fusedAG<<<N_TOTAL + NGEMM, 256, sizeof(GS)>>>(price, news, mask, router_W);

    cudaFuncSetAttribute(kernelC,
                         cudaFuncAttributeMaxDynamicSharedMemorySize,
                         (int)sizeof(SmemC));
    kernelC<<<256, 256, sizeof(SmemC)>>>(
        router_b, gate_W, gate_b, expert_W, expert_b,
        wq, wq_b, wk, wk_b, wv, wv_b, wo, wo_b, out);
}